// round 3
// baseline (speedup 1.0000x reference)
#include <cuda_runtime.h>
#include <cuda_fp16.h>
#include <cstdint>

#define OUT_F   11008
#define IN_F    4096
#define TOK     16
#define TILE_M  128
#define THREADS 256
#define S128    (IN_F / 128)        // 32 outer steps of 128 k
#define XH_STRIDE 8224              // 4096*2 + 32B pad (bank-conflict-free)
#define SMEM_BYTES (TOK * XH_STRIDE)  // 131584

// ---------------- helpers ----------------
__device__ __forceinline__ uint32_t smem_u32(const void* p) {
    uint32_t a;
    asm("{ .reg .u64 t; cvta.to.shared.u64 t, %1; cvt.u32.u64 %0, t; }" : "=r"(a) : "l"(p));
    return a;
}
__device__ __forceinline__ unsigned long long pack2(unsigned int lo, unsigned int hi) {
    unsigned long long d; asm("mov.b64 %0, {%1,%2};" : "=l"(d) : "r"(lo), "r"(hi)); return d;
}
__device__ __forceinline__ unsigned long long add2(unsigned long long a, unsigned long long b) {
    unsigned long long d; asm("add.rn.f32x2 %0, %1, %2;" : "=l"(d) : "l"(a), "l"(b)); return d;
}
__device__ __forceinline__ unsigned long long mul2(unsigned long long a, unsigned long long b) {
    unsigned long long d; asm("mul.rn.f32x2 %0, %1, %2;" : "=l"(d) : "l"(a), "l"(b)); return d;
}
// q0,q1 in [0,15] -> fp16x2 {s*(q0-8), s*(q1-8)}; fp32-exact dequant, one fp16 round.
__device__ __forceinline__ uint32_t dqh(int q0, int q1, unsigned long long s2) {
    const unsigned long long M2 = pack2(0xCB000008u, 0xCB000008u); // -8388616.0f x2
    unsigned long long f = pack2(0x4B000000u | (unsigned)q0, 0x4B000000u | (unsigned)q1);
    unsigned long long w = mul2(add2(f, M2), s2);
    unsigned int l, h;
    asm("mov.b64 {%0,%1}, %2;" : "=r"(l), "=r"(h) : "l"(w));
    uint32_t r;
    asm("cvt.rn.f16x2.f32 %0, %1, %2;" : "=r"(r)
        : "f"(__uint_as_float(h)), "f"(__uint_as_float(l)));
    return r;
}
__device__ __forceinline__ void mma16816(float* c, uint32_t a0, uint32_t a1,
                                         uint32_t a2, uint32_t a3,
                                         uint32_t b0, uint32_t b1) {
    asm volatile(
        "mma.sync.aligned.m16n8k16.row.col.f32.f16.f16.f32 "
        "{%0,%1,%2,%3}, {%4,%5,%6,%7}, {%8,%9}, {%0,%1,%2,%3};"
        : "+f"(c[0]), "+f"(c[1]), "+f"(c[2]), "+f"(c[3])
        : "r"(a0), "r"(a1), "r"(a2), "r"(a3), "r"(b0), "r"(b1));
}

__global__ void __launch_bounds__(THREADS, 1)
qlin(const float* __restrict__ x, const int* __restrict__ qw,
     const float* __restrict__ scales, const float* __restrict__ bias,
     float* __restrict__ y)
{
    extern __shared__ char smem[];
    const uint32_t sb = smem_u32(smem);
    const int tid = threadIdx.x;

    // ---- phase 1: x (16x4096 fp32) -> fp16 smem tile, padded rows ----
    for (int i = tid; i < TOK * IN_F / 4; i += THREADS) {
        int tok = i >> 10, kq = i & 1023;
        float4 v = __ldg(reinterpret_cast<const float4*>(x) + i);
        uint32_t h01, h23;
        asm("cvt.rn.f16x2.f32 %0, %1, %2;" : "=r"(h01) : "f"(v.y), "f"(v.x));
        asm("cvt.rn.f16x2.f32 %0, %1, %2;" : "=r"(h23) : "f"(v.w), "f"(v.z));
        asm volatile("st.shared.v2.b32 [%0], {%1,%2};"
                     :: "r"(sb + tok * XH_STRIDE + kq * 8), "r"(h01), "r"(h23) : "memory");
    }
    __syncthreads();

    // ---- phase 2: per-warp 16-row GEMV via mma.sync ----
    const int lane = tid & 31, wid = tid >> 5;
    const int g = lane >> 2, t = lane & 3;
    const int rowA = blockIdx.x * TILE_M + wid * 16 + g;
    const int rowB = rowA + 8;

    const int4* qA = reinterpret_cast<const int4*>(qw + (size_t)rowA * IN_F) + t;
    const int4* qB = reinterpret_cast<const int4*>(qw + (size_t)rowB * IN_F) + t;
    const float4* sA4 = reinterpret_cast<const float4*>(scales + (size_t)rowA * 128);
    const float4* sB4 = reinterpret_cast<const float4*>(scales + (size_t)rowB * 128);

    const uint32_t xb0 = sb + g * XH_STRIDE + t * 8;        // B half0: toks 0..7
    const uint32_t xb1 = sb + (g + 8) * XH_STRIDE + t * 8;  // B half1: toks 8..15

    float acc0[4] = {0.f, 0.f, 0.f, 0.f};
    float acc1[4] = {0.f, 0.f, 0.f, 0.f};

    int4 ra[2][8], rb[2][8];
    float4 sc[2][2];

    #pragma unroll
    for (int c = 0; c < 8; c++) {
        ra[0][c] = __ldg(qA + c * 4);
        rb[0][c] = __ldg(qB + c * 4);
    }
    sc[0][0] = __ldg(sA4);
    sc[0][1] = __ldg(sB4);

    #pragma unroll 1
    for (int s = 0; s < S128; s++) {
        const int cur = s & 1, nxt = cur ^ 1;
        const int sn = (s + 1 < S128) ? s + 1 : s;

        // prefetch next 128-k slice (16 int4 + 2 float4 in flight)
        #pragma unroll
        for (int c = 0; c < 8; c++) {
            ra[nxt][c] = __ldg(qA + sn * 32 + c * 4);
            rb[nxt][c] = __ldg(qB + sn * 32 + c * 4);
        }
        sc[nxt][0] = __ldg(sA4 + sn);
        sc[nxt][1] = __ldg(sB4 + sn);

        const float* fsA = reinterpret_cast<const float*>(&sc[cur][0]);
        const float* fsB = reinterpret_cast<const float*>(&sc[cur][1]);

        #pragma unroll
        for (int c = 0; c < 8; c++) {
            const float sa = fsA[c >> 1], sbv = fsB[c >> 1];
            unsigned long long s2a = pack2(__float_as_uint(sa), __float_as_uint(sa));
            unsigned long long s2b = pack2(__float_as_uint(sbv), __float_as_uint(sbv));
            int4 va = ra[cur][c], vb = rb[cur][c];
            uint32_t a0 = dqh(va.x, va.y, s2a);   // row g,   phys k 4t,4t+1
            uint32_t a1 = dqh(vb.x, vb.y, s2b);   // row g+8
            uint32_t a2 = dqh(va.z, va.w, s2a);   // row g,   phys k 4t+2,4t+3
            uint32_t a3 = dqh(vb.z, vb.w, s2b);

            const uint32_t koff = (uint32_t)(s * 256 + c * 32); // bytes
            uint32_t b0, b1, c0, c1;
            asm volatile("ld.shared.v2.b32 {%0,%1}, [%2];"
                         : "=r"(b0), "=r"(b1) : "r"(xb0 + koff));
            asm volatile("ld.shared.v2.b32 {%0,%1}, [%2];"
                         : "=r"(c0), "=r"(c1) : "r"(xb1 + koff));
            mma16816(acc0, a0, a1, a2, a3, b0, b1);
            mma16816(acc1, a0, a1, a2, a3, c0, c1);
        }
    }

    // ---- epilogue: C frag -> y (tok = n for half0, n+8 for half1) ----
    const float bA = __ldg(bias + rowA);
    const float bB = __ldg(bias + rowB);
    const int tok0 = 2 * t;
    float* yA = y + rowA;
    float* yB = y + rowB;
    yA[(size_t)(tok0    ) * OUT_F] = acc0[0] + bA;
    yA[(size_t)(tok0 + 1) * OUT_F] = acc0[1] + bA;
    yB[(size_t)(tok0    ) * OUT_F] = acc0[2] + bB;
    yB[(size_t)(tok0 + 1) * OUT_F] = acc0[3] + bB;
    yA[(size_t)(tok0 + 8) * OUT_F] = acc1[0] + bA;
    yA[(size_t)(tok0 + 9) * OUT_F] = acc1[1] + bA;
    yB[(size_t)(tok0 + 8) * OUT_F] = acc1[2] + bB;
    yB[(size_t)(tok0 + 9) * OUT_F] = acc1[3] + bB;
}

extern "C" void kernel_launch(void* const* d_in, const int* in_sizes, int n_in,
                              void* d_out, int out_size)
{
    const float* x      = (const float*)d_in[0];
    const int*   qw     = (const int*)d_in[1];
    const float* scales = (const float*)d_in[2];
    const float* bias   = (const float*)d_in[3];
    float*       y      = (float*)d_out;

    cudaFuncSetAttribute(qlin, cudaFuncAttributeMaxDynamicSharedMemorySize, SMEM_BYTES);
    qlin<<<OUT_F / TILE_M, THREADS, SMEM_BYTES>>>(x, qw, scales, bias, y);
}

// round 4
// speedup vs baseline: 1.9803x; 1.9803x over previous
#include <cuda_runtime.h>
#include <cuda_fp16.h>
#include <cstdint>

#define OUT_F   11008
#define IN_F    4096
#define TOK     16
#define TILE_M  128
#define KSPLIT  8
#define KCHUNK  (IN_F / KSPLIT)    // 512
#define STEPS   (KCHUNK / 64)      // 8 steps of 64 k
#define THREADS 256

__device__ __half g_xh[TOK * IN_F];                       // x as fp16, [tok][k]
__device__ float  g_partial[(size_t)KSPLIT * OUT_F * TOK]; // [split][o][tok]

// ---------------- helpers ----------------
__device__ __forceinline__ unsigned long long pack2(unsigned int lo, unsigned int hi) {
    unsigned long long d; asm("mov.b64 %0, {%1,%2};" : "=l"(d) : "r"(lo), "r"(hi)); return d;
}
__device__ __forceinline__ unsigned long long add2(unsigned long long a, unsigned long long b) {
    unsigned long long d; asm("add.rn.f32x2 %0, %1, %2;" : "=l"(d) : "l"(a), "l"(b)); return d;
}
__device__ __forceinline__ unsigned long long mul2(unsigned long long a, unsigned long long b) {
    unsigned long long d; asm("mul.rn.f32x2 %0, %1, %2;" : "=l"(d) : "l"(a), "l"(b)); return d;
}
// q0,q1 in [0,15] -> fp16x2 {s*(q0-8), s*(q1-8)}; fp32-exact dequant, one fp16 round.
__device__ __forceinline__ uint32_t dqh(int q0, int q1, unsigned long long s2) {
    const unsigned long long M2 = pack2(0xCB000008u, 0xCB000008u); // -8388616.0f x2
    unsigned long long f = pack2(0x4B000000u | (unsigned)q0, 0x4B000000u | (unsigned)q1);
    unsigned long long w = mul2(add2(f, M2), s2);
    unsigned int l, h;
    asm("mov.b64 {%0,%1}, %2;" : "=r"(l), "=r"(h) : "l"(w));
    uint32_t r;
    asm("cvt.rn.f16x2.f32 %0, %1, %2;" : "=r"(r)
        : "f"(__uint_as_float(h)), "f"(__uint_as_float(l)));
    return r;
}
__device__ __forceinline__ void mma16816(float* c, uint32_t a0, uint32_t a1,
                                         uint32_t a2, uint32_t a3,
                                         uint32_t b0, uint32_t b1) {
    asm volatile(
        "mma.sync.aligned.m16n8k16.row.col.f32.f16.f16.f32 "
        "{%0,%1,%2,%3}, {%4,%5,%6,%7}, {%8,%9}, {%0,%1,%2,%3};"
        : "+f"(c[0]), "+f"(c[1]), "+f"(c[2]), "+f"(c[3])
        : "r"(a0), "r"(a1), "r"(a2), "r"(a3), "r"(b0), "r"(b1));
}

// ---------------- kernel 1: x fp32 -> fp16 ----------------
__global__ void xconv(const float* __restrict__ x) {
    int i = blockIdx.x * 256 + threadIdx.x;      // float4 index, 16384 total
    float4 v = __ldg(reinterpret_cast<const float4*>(x) + i);
    uint32_t h01, h23;
    asm("cvt.rn.f16x2.f32 %0, %1, %2;" : "=r"(h01) : "f"(v.y), "f"(v.x));
    asm("cvt.rn.f16x2.f32 %0, %1, %2;" : "=r"(h23) : "f"(v.w), "f"(v.z));
    reinterpret_cast<uint2*>(g_xh)[i] = make_uint2(h01, h23);
}

// ---------------- kernel 2: quantized GEMM into partials ----------------
// k permutation within a 64-k step: c=(j,p) uses k = 32j + 8t + 4p + {0..3}
// A int4 idx (per row, from step base): 8j + 2t + p ; B: halves 8t.. of LDG.128 at 32j.
__device__ __forceinline__ void step_body(
    int s, int sn,
    const int4 (&curA)[4], const int4 (&curB)[4],
    int4 (&nxtA)[4], int4 (&nxtB)[4],
    const int4* qA, const int4* qB,
    const float2* sA, const float2* sB,
    const __half* xh0, const __half* xh1,
    float (&acc)[2][4])
{
    // prefetch next step's A (8 LDG.128 in flight while computing cur)
    #pragma unroll
    for (int j2 = 0; j2 < 4; j2++) {
        int idx = sn * 16 + (j2 >> 1) * 8 + (j2 & 1);   // 2t folded into qA/qB
        nxtA[j2] = __ldg(qA + idx);
        nxtB[j2] = __ldg(qB + idx);
    }

    // B fragments: 4x LDG.128 from fp16 x (L1/L2 resident)
    uint4 bh[2][2];
    #pragma unroll
    for (int j = 0; j < 2; j++) {
        bh[0][j] = *reinterpret_cast<const uint4*>(xh0 + s * 64 + 32 * j);
        bh[1][j] = *reinterpret_cast<const uint4*>(xh1 + s * 64 + 32 * j);
    }

    float2 scA = __ldg(sA + s);   // blocks 2s (j=0), 2s+1 (j=1)
    float2 scB = __ldg(sB + s);

    #pragma unroll
    for (int j = 0; j < 2; j++) {
        float sa = j ? scA.y : scA.x;
        float sb = j ? scB.y : scB.x;
        unsigned long long s2a = pack2(__float_as_uint(sa), __float_as_uint(sa));
        unsigned long long s2b = pack2(__float_as_uint(sb), __float_as_uint(sb));
        #pragma unroll
        for (int p = 0; p < 2; p++) {
            int4 va = curA[2 * j + p], vb = curB[2 * j + p];
            uint32_t a0 = dqh(va.x, va.y, s2a);
            uint32_t a2 = dqh(va.z, va.w, s2a);
            uint32_t a1 = dqh(vb.x, vb.y, s2b);
            uint32_t a3 = dqh(vb.z, vb.w, s2b);
            const uint32_t* b0 = reinterpret_cast<const uint32_t*>(&bh[0][j]);
            const uint32_t* b1 = reinterpret_cast<const uint32_t*>(&bh[1][j]);
            mma16816(acc[0], a0, a1, a2, a3, b0[2 * p], b0[2 * p + 1]);
            mma16816(acc[1], a0, a1, a2, a3, b1[2 * p], b1[2 * p + 1]);
        }
    }
}

__global__ void __launch_bounds__(THREADS, 2)
qmma(const int* __restrict__ qw, const float* __restrict__ scales)
{
    const int lane = threadIdx.x & 31, wid = threadIdx.x >> 5;
    const int g = lane >> 2, t = lane & 3;
    const int rowA = blockIdx.x * TILE_M + wid * 16 + g;
    const int rowB = rowA + 8;
    const int k0 = blockIdx.y * KCHUNK;

    const int4* qA = reinterpret_cast<const int4*>(qw + (size_t)rowA * IN_F + k0) + 2 * t;
    const int4* qB = reinterpret_cast<const int4*>(qw + (size_t)rowB * IN_F + k0) + 2 * t;
    const float2* sA = reinterpret_cast<const float2*>(scales + (size_t)rowA * (IN_F / 32) + k0 / 32);
    const float2* sB = reinterpret_cast<const float2*>(scales + (size_t)rowB * (IN_F / 32) + k0 / 32);
    const __half* xh0 = g_xh + (size_t)g * IN_F + k0 + 8 * t;        // tokens 0..7
    const __half* xh1 = g_xh + (size_t)(g + 8) * IN_F + k0 + 8 * t;  // tokens 8..15

    float acc[2][4] = {};
    int4 b0A[4], b0B[4], b1A[4], b1B[4];

    #pragma unroll
    for (int j2 = 0; j2 < 4; j2++) {
        int idx = (j2 >> 1) * 8 + (j2 & 1);
        b0A[j2] = __ldg(qA + idx);
        b0B[j2] = __ldg(qB + idx);
    }

    #pragma unroll 1
    for (int s = 0; s < STEPS; s += 2) {
        step_body(s,     s + 1,                         b0A, b0B, b1A, b1B,
                  qA, qB, sA, sB, xh0, xh1, acc);
        step_body(s + 1, (s + 2 < STEPS) ? s + 2 : s + 1, b1A, b1B, b0A, b0B,
                  qA, qB, sA, sB, xh0, xh1, acc);
    }

    // partials [split][o][tok]: warp writes 16 rows x 16 toks contiguous
    float* out = g_partial + (size_t)blockIdx.y * OUT_F * TOK;
    float* pa = out + (size_t)rowA * TOK + 2 * t;
    float* pb = out + (size_t)rowB * TOK + 2 * t;
    *reinterpret_cast<float2*>(pa)     = make_float2(acc[0][0], acc[0][1]);
    *reinterpret_cast<float2*>(pa + 8) = make_float2(acc[1][0], acc[1][1]);
    *reinterpret_cast<float2*>(pb)     = make_float2(acc[0][2], acc[0][3]);
    *reinterpret_cast<float2*>(pb + 8) = make_float2(acc[1][2], acc[1][3]);
}

// ---------------- kernel 3: reduce splits + bias ----------------
__global__ void qreduce(const float* __restrict__ bias, float* __restrict__ y)
{
    const int tid = threadIdx.x;
    const int tok = tid & 15;
    const int o = blockIdx.x * 16 + (tid >> 4);
    float acc = __ldg(bias + o);
    #pragma unroll
    for (int s = 0; s < KSPLIT; s++)
        acc += g_partial[((size_t)s * OUT_F + o) * TOK + tok];
    y[(size_t)tok * OUT_F + o] = acc;
}

extern "C" void kernel_launch(void* const* d_in, const int* in_sizes, int n_in,
                              void* d_out, int out_size)
{
    const float* x      = (const float*)d_in[0];
    const int*   qw     = (const int*)d_in[1];
    const float* scales = (const float*)d_in[2];
    const float* bias   = (const float*)d_in[3];
    float*       y      = (float*)d_out;

    xconv  <<<TOK * IN_F / 4 / 256, 256>>>(x);
    qmma   <<<dim3(OUT_F / TILE_M, KSPLIT), THREADS>>>(qw, scales);
    qreduce<<<OUT_F / 16, 256>>>(bias, y);
}

// round 5
// speedup vs baseline: 2.1964x; 1.1091x over previous
#include <cuda_runtime.h>
#include <cuda_fp16.h>
#include <cstdint>

#define OUT_F   11008
#define IN_F    4096
#define TOK     16
#define TILE_M  128
#define KSPLIT  8
#define KCHUNK  (IN_F / KSPLIT)    // 512
#define STEPS   (KCHUNK / 64)      // 8 steps of 64 k
#define THREADS 256
#define XROW    1040               // 512 halves * 2B + 16B pad (bank-stagger)

__device__ float g_partial[(size_t)KSPLIT * OUT_F * TOK]; // [split][o][tok]

// ---------------- helpers ----------------
__device__ __forceinline__ uint32_t smem_u32(const void* p) {
    uint32_t a;
    asm("{ .reg .u64 t; cvta.to.shared.u64 t, %1; cvt.u32.u64 %0, t; }" : "=r"(a) : "l"(p));
    return a;
}
__device__ __forceinline__ unsigned long long pack2(unsigned int lo, unsigned int hi) {
    unsigned long long d; asm("mov.b64 %0, {%1,%2};" : "=l"(d) : "r"(lo), "r"(hi)); return d;
}
__device__ __forceinline__ unsigned long long add2(unsigned long long a, unsigned long long b) {
    unsigned long long d; asm("add.rn.f32x2 %0, %1, %2;" : "=l"(d) : "l"(a), "l"(b)); return d;
}
__device__ __forceinline__ unsigned long long mul2(unsigned long long a, unsigned long long b) {
    unsigned long long d; asm("mul.rn.f32x2 %0, %1, %2;" : "=l"(d) : "l"(a), "l"(b)); return d;
}
// q0,q1 in [0,15] -> fp16x2 {s*(q0-8), s*(q1-8)}; fp32-exact dequant, one fp16 round.
__device__ __forceinline__ uint32_t dqh(int q0, int q1, unsigned long long s2) {
    const unsigned long long M2 = pack2(0xCB000008u, 0xCB000008u); // -8388616.0f x2
    unsigned long long f = pack2(0x4B000000u | (unsigned)q0, 0x4B000000u | (unsigned)q1);
    unsigned long long w = mul2(add2(f, M2), s2);
    unsigned int l, h;
    asm("mov.b64 {%0,%1}, %2;" : "=r"(l), "=r"(h) : "l"(w));
    uint32_t r;
    asm("cvt.rn.f16x2.f32 %0, %1, %2;" : "=r"(r)
        : "f"(__uint_as_float(h)), "f"(__uint_as_float(l)));
    return r;
}
__device__ __forceinline__ void mma16816(float* c, uint32_t a0, uint32_t a1,
                                         uint32_t a2, uint32_t a3,
                                         uint32_t b0, uint32_t b1) {
    asm volatile(
        "mma.sync.aligned.m16n8k16.row.col.f32.f16.f16.f32 "
        "{%0,%1,%2,%3}, {%4,%5,%6,%7}, {%8,%9}, {%0,%1,%2,%3};"
        : "+f"(c[0]), "+f"(c[1]), "+f"(c[2]), "+f"(c[3])
        : "r"(a0), "r"(a1), "r"(a2), "r"(a3), "r"(b0), "r"(b1));
}

// ---------------- main kernel: fused convert + quantized GEMM ----------------
// k permutation within a 64-k step: c=(j,p) uses k = 32j + 8t + 4p + {0..3}
__device__ __forceinline__ void step_body(
    int s, int sn,
    const int4 (&curA)[4], const int4 (&curB)[4],
    int4 (&nxtA)[4], int4 (&nxtB)[4],
    const int4* qA, const int4* qB,
    const float2* sA, const float2* sB,
    uint32_t xb0, uint32_t xb1,
    float (&acc)[2][4])
{
    // prefetch next step's A: 8 LDG.128, evict-first (streaming, zero reuse)
    #pragma unroll
    for (int j2 = 0; j2 < 4; j2++) {
        int idx = sn * 16 + (j2 >> 1) * 8 + (j2 & 1);
        nxtA[j2] = __ldcs(qA + idx);
        nxtB[j2] = __ldcs(qB + idx);
    }

    // B fragments: 4x LDS.128 from fp16 x tile
    uint4 bh[2][2];
    #pragma unroll
    for (int j = 0; j < 2; j++) {
        asm volatile("ld.shared.v4.b32 {%0,%1,%2,%3}, [%4];"
            : "=r"(bh[0][j].x), "=r"(bh[0][j].y), "=r"(bh[0][j].z), "=r"(bh[0][j].w)
            : "r"(xb0 + (uint32_t)(s * 128 + 64 * j)));
        asm volatile("ld.shared.v4.b32 {%0,%1,%2,%3}, [%4];"
            : "=r"(bh[1][j].x), "=r"(bh[1][j].y), "=r"(bh[1][j].z), "=r"(bh[1][j].w)
            : "r"(xb1 + (uint32_t)(s * 128 + 64 * j)));
    }

    float2 scA = __ldg(sA + s);   // blocks 2s (j=0), 2s+1 (j=1)
    float2 scB = __ldg(sB + s);

    #pragma unroll
    for (int j = 0; j < 2; j++) {
        float sa = j ? scA.y : scA.x;
        float sb = j ? scB.y : scB.x;
        unsigned long long s2a = pack2(__float_as_uint(sa), __float_as_uint(sa));
        unsigned long long s2b = pack2(__float_as_uint(sb), __float_as_uint(sb));
        #pragma unroll
        for (int p = 0; p < 2; p++) {
            int4 va = curA[2 * j + p], vb = curB[2 * j + p];
            uint32_t a0 = dqh(va.x, va.y, s2a);
            uint32_t a2 = dqh(va.z, va.w, s2a);
            uint32_t a1 = dqh(vb.x, vb.y, s2b);
            uint32_t a3 = dqh(vb.z, vb.w, s2b);
            const uint32_t* b0 = reinterpret_cast<const uint32_t*>(&bh[0][j]);
            const uint32_t* b1 = reinterpret_cast<const uint32_t*>(&bh[1][j]);
            mma16816(acc[0], a0, a1, a2, a3, b0[2 * p], b0[2 * p + 1]);
            mma16816(acc[1], a0, a1, a2, a3, b1[2 * p], b1[2 * p + 1]);
        }
    }
}

__global__ void __launch_bounds__(THREADS, 2)
qmma(const float* __restrict__ x, const int* __restrict__ qw,
     const float* __restrict__ scales)
{
    __shared__ __align__(16) char xs[TOK * XROW];   // 16.6 KB fp16 x tile
    const uint32_t sb = smem_u32(xs);

    const int tid = threadIdx.x;
    const int lane = tid & 31, wid = tid >> 5;
    const int g = lane >> 2, t = lane & 3;
    const int rowA = blockIdx.x * TILE_M + wid * 16 + g;
    const int rowB = rowA + 8;
    const int k0 = blockIdx.y * KCHUNK;

    const int4* qA = reinterpret_cast<const int4*>(qw + (size_t)rowA * IN_F + k0) + 2 * t;
    const int4* qB = reinterpret_cast<const int4*>(qw + (size_t)rowB * IN_F + k0) + 2 * t;
    const float2* sA = reinterpret_cast<const float2*>(scales + (size_t)rowA * (IN_F / 32) + k0 / 32);
    const float2* sB = reinterpret_cast<const float2*>(scales + (size_t)rowB * (IN_F / 32) + k0 / 32);

    float acc[2][4] = {};
    int4 b0A[4], b0B[4], b1A[4], b1B[4];

    // start the qweight DRAM stream immediately (before x conversion)
    #pragma unroll
    for (int j2 = 0; j2 < 4; j2++) {
        int idx = (j2 >> 1) * 8 + (j2 & 1);
        b0A[j2] = __ldcs(qA + idx);
        b0B[j2] = __ldcs(qB + idx);
    }

    // fused x conversion: this CTA's 16x512 fp32 slice -> fp16 smem
    #pragma unroll
    for (int it = 0; it < 8; it++) {
        int i = tid + it * THREADS;          // 0..2047 float4 slots
        int tok = i >> 7, kq = i & 127;      // 128 float4 per token row
        float4 v = __ldg(reinterpret_cast<const float4*>(x + (size_t)tok * IN_F + k0) + kq);
        uint32_t h01, h23;
        asm("cvt.rn.f16x2.f32 %0, %1, %2;" : "=r"(h01) : "f"(v.y), "f"(v.x));
        asm("cvt.rn.f16x2.f32 %0, %1, %2;" : "=r"(h23) : "f"(v.w), "f"(v.z));
        asm volatile("st.shared.v2.b32 [%0], {%1,%2};"
                     :: "r"(sb + (uint32_t)(tok * XROW + kq * 8)), "r"(h01), "r"(h23) : "memory");
    }
    __syncthreads();

    const uint32_t xb0 = sb + (uint32_t)(g * XROW + 16 * t);         // tokens 0..7
    const uint32_t xb1 = sb + (uint32_t)((g + 8) * XROW + 16 * t);   // tokens 8..15

    #pragma unroll 1
    for (int s = 0; s < STEPS; s += 2) {
        step_body(s,     s + 1,                           b0A, b0B, b1A, b1B,
                  qA, qB, sA, sB, xb0, xb1, acc);
        step_body(s + 1, (s + 2 < STEPS) ? s + 2 : s + 1, b1A, b1B, b0A, b0B,
                  qA, qB, sA, sB, xb0, xb1, acc);
    }

    // partials [split][o][tok]: warp writes 16 rows x 16 toks contiguous
    float* out = g_partial + (size_t)blockIdx.y * OUT_F * TOK;
    float* pa = out + (size_t)rowA * TOK + 2 * t;
    float* pb = out + (size_t)rowB * TOK + 2 * t;
    *reinterpret_cast<float2*>(pa)     = make_float2(acc[0][0], acc[0][1]);
    *reinterpret_cast<float2*>(pa + 8) = make_float2(acc[1][0], acc[1][1]);
    *reinterpret_cast<float2*>(pb)     = make_float2(acc[0][2], acc[0][3]);
    *reinterpret_cast<float2*>(pb + 8) = make_float2(acc[1][2], acc[1][3]);
}

// ---------------- reduce splits + bias ----------------
__global__ void qreduce(const float* __restrict__ bias, float* __restrict__ y)
{
    const int tid = threadIdx.x;
    const int tok = tid & 15;
    const int o = blockIdx.x * 16 + (tid >> 4);
    float acc = __ldg(bias + o);
    #pragma unroll
    for (int s = 0; s < KSPLIT; s++)
        acc += g_partial[((size_t)s * OUT_F + o) * TOK + tok];
    y[(size_t)tok * OUT_F + o] = acc;
}

extern "C" void kernel_launch(void* const* d_in, const int* in_sizes, int n_in,
                              void* d_out, int out_size)
{
    const float* x      = (const float*)d_in[0];
    const int*   qw     = (const int*)d_in[1];
    const float* scales = (const float*)d_in[2];
    const float* bias   = (const float*)d_in[3];
    float*       y      = (float*)d_out;

    qmma   <<<dim3(OUT_F / TILE_M, KSPLIT), THREADS>>>(x, qw, scales);
    qreduce<<<OUT_F / 16, 256>>>(bias, y);
}

// round 6
// speedup vs baseline: 2.5342x; 1.1538x over previous
#include <cuda_runtime.h>
#include <cuda_fp16.h>
#include <cstdint>

#define OUT_F   11008
#define IN_F    4096
#define TOK     16
#define TILE_M  128
#define KSPLIT  32
#define KCHUNK  (IN_F / KSPLIT)    // 128
#define STEPS   (KCHUNK / 64)      // 2 steps of 64 k
#define THREADS 256
#define XROW    (KCHUNK * 2 + 16)  // 272 B padded row

// ---------------- helpers ----------------
__device__ __forceinline__ uint32_t smem_u32(const void* p) {
    uint32_t a;
    asm("{ .reg .u64 t; cvta.to.shared.u64 t, %1; cvt.u32.u64 %0, t; }" : "=r"(a) : "l"(p));
    return a;
}
__device__ __forceinline__ unsigned long long pack2(unsigned int lo, unsigned int hi) {
    unsigned long long d; asm("mov.b64 %0, {%1,%2};" : "=l"(d) : "r"(lo), "r"(hi)); return d;
}
__device__ __forceinline__ unsigned long long add2(unsigned long long a, unsigned long long b) {
    unsigned long long d; asm("add.rn.f32x2 %0, %1, %2;" : "=l"(d) : "l"(a), "l"(b)); return d;
}
__device__ __forceinline__ unsigned long long mul2(unsigned long long a, unsigned long long b) {
    unsigned long long d; asm("mul.rn.f32x2 %0, %1, %2;" : "=l"(d) : "l"(a), "l"(b)); return d;
}
// q0,q1 in [0,15] -> fp16x2 {s*(q0-8), s*(q1-8)}; fp32-exact dequant, one fp16 round.
__device__ __forceinline__ uint32_t dqh(int q0, int q1, unsigned long long s2) {
    const unsigned long long M2 = pack2(0xCB000008u, 0xCB000008u); // -8388616.0f x2
    unsigned long long f = pack2(0x4B000000u | (unsigned)q0, 0x4B000000u | (unsigned)q1);
    unsigned long long w = mul2(add2(f, M2), s2);
    unsigned int l, h;
    asm("mov.b64 {%0,%1}, %2;" : "=r"(l), "=r"(h) : "l"(w));
    uint32_t r;
    asm("cvt.rn.f16x2.f32 %0, %1, %2;" : "=r"(r)
        : "f"(__uint_as_float(h)), "f"(__uint_as_float(l)));
    return r;
}
__device__ __forceinline__ void mma16816(float* c, uint32_t a0, uint32_t a1,
                                         uint32_t a2, uint32_t a3,
                                         uint32_t b0, uint32_t b1) {
    asm volatile(
        "mma.sync.aligned.m16n8k16.row.col.f32.f16.f16.f32 "
        "{%0,%1,%2,%3}, {%4,%5,%6,%7}, {%8,%9}, {%0,%1,%2,%3};"
        : "+f"(c[0]), "+f"(c[1]), "+f"(c[2]), "+f"(c[3])
        : "r"(a0), "r"(a1), "r"(a2), "r"(a3), "r"(b0), "r"(b1));
}

// ---------------- kernel 1: y = bias (broadcast over tokens) ----------------
__global__ void yinit(const float* __restrict__ bias, float* __restrict__ y)
{
    int i = blockIdx.x * 256 + threadIdx.x;      // float4 idx, 44032 total
    int tok = i / (OUT_F / 4);
    int o4  = i - tok * (OUT_F / 4);
    float4 b = __ldg(reinterpret_cast<const float4*>(bias) + o4);
    reinterpret_cast<float4*>(y)[i] = b;
}

// ---------------- kernel 2: fused convert + quantized GEMM, atomic epilogue --
// k permutation within a 64-k step: c=(j,p) uses k = 64s + 32j + 8t + 4p + {0..3}
__device__ __forceinline__ void step_body(
    int s, int sn, bool pf,
    const int4 (&curA)[4], const int4 (&curB)[4],
    int4 (&nxtA)[4], int4 (&nxtB)[4],
    const int4* qA, const int4* qB,
    const float2* sA, const float2* sB,
    uint32_t xb0, uint32_t xb1,
    float (&acc)[2][4])
{
    if (pf) {
        // prefetch next step's A: 8 LDG.128, evict-first (streaming, zero reuse)
        #pragma unroll
        for (int j2 = 0; j2 < 4; j2++) {
            int idx = sn * 16 + (j2 >> 1) * 8 + (j2 & 1);
            nxtA[j2] = __ldcs(qA + idx);
            nxtB[j2] = __ldcs(qB + idx);
        }
    }

    // B fragments: 4x LDS.128 from fp16 x tile
    uint4 bh[2][2];
    #pragma unroll
    for (int j = 0; j < 2; j++) {
        asm volatile("ld.shared.v4.b32 {%0,%1,%2,%3}, [%4];"
            : "=r"(bh[0][j].x), "=r"(bh[0][j].y), "=r"(bh[0][j].z), "=r"(bh[0][j].w)
            : "r"(xb0 + (uint32_t)(s * 128 + 64 * j)));
        asm volatile("ld.shared.v4.b32 {%0,%1,%2,%3}, [%4];"
            : "=r"(bh[1][j].x), "=r"(bh[1][j].y), "=r"(bh[1][j].z), "=r"(bh[1][j].w)
            : "r"(xb1 + (uint32_t)(s * 128 + 64 * j)));
    }

    float2 scA = __ldg(sA + s);   // blocks 2s (j=0), 2s+1 (j=1)
    float2 scB = __ldg(sB + s);

    #pragma unroll
    for (int j = 0; j < 2; j++) {
        float sa = j ? scA.y : scA.x;
        float sb = j ? scB.y : scB.x;
        unsigned long long s2a = pack2(__float_as_uint(sa), __float_as_uint(sa));
        unsigned long long s2b = pack2(__float_as_uint(sb), __float_as_uint(sb));
        #pragma unroll
        for (int p = 0; p < 2; p++) {
            int4 va = curA[2 * j + p], vb = curB[2 * j + p];
            uint32_t a0 = dqh(va.x, va.y, s2a);
            uint32_t a2 = dqh(va.z, va.w, s2a);
            uint32_t a1 = dqh(vb.x, vb.y, s2b);
            uint32_t a3 = dqh(vb.z, vb.w, s2b);
            const uint32_t* b0 = reinterpret_cast<const uint32_t*>(&bh[0][j]);
            const uint32_t* b1 = reinterpret_cast<const uint32_t*>(&bh[1][j]);
            mma16816(acc[0], a0, a1, a2, a3, b0[2 * p], b0[2 * p + 1]);
            mma16816(acc[1], a0, a1, a2, a3, b1[2 * p], b1[2 * p + 1]);
        }
    }
}

__global__ void __launch_bounds__(THREADS, 4)
qmma(const float* __restrict__ x, const int* __restrict__ qw,
     const float* __restrict__ scales, float* __restrict__ y)
{
    __shared__ __align__(16) char xs[TOK * XROW];   // 4.4 KB fp16 x tile
    const uint32_t sb = smem_u32(xs);

    const int tid = threadIdx.x;
    const int lane = tid & 31, wid = tid >> 5;
    const int g = lane >> 2, t = lane & 3;
    const int rowA = blockIdx.x * TILE_M + wid * 16 + g;
    const int rowB = rowA + 8;
    const int k0 = blockIdx.y * KCHUNK;

    const int4* qA = reinterpret_cast<const int4*>(qw + (size_t)rowA * IN_F + k0) + 2 * t;
    const int4* qB = reinterpret_cast<const int4*>(qw + (size_t)rowB * IN_F + k0) + 2 * t;
    const float2* sA = reinterpret_cast<const float2*>(scales + (size_t)rowA * (IN_F / 32) + k0 / 32);
    const float2* sB = reinterpret_cast<const float2*>(scales + (size_t)rowB * (IN_F / 32) + k0 / 32);

    float acc[2][4] = {};
    int4 b0A[4], b0B[4], b1A[4], b1B[4];

    // start the qweight DRAM stream immediately (before x conversion)
    #pragma unroll
    for (int j2 = 0; j2 < 4; j2++) {
        int idx = (j2 >> 1) * 8 + (j2 & 1);
        b0A[j2] = __ldcs(qA + idx);
        b0B[j2] = __ldcs(qB + idx);
    }

    // fused x conversion: this CTA's 16x128 fp32 slice -> fp16 smem (2 float4/thread)
    #pragma unroll
    for (int it = 0; it < TOK * KCHUNK / 4 / THREADS; it++) {
        int i = tid + it * THREADS;                  // float4 slots
        int tok = i >> 5, kq = i & 31;               // 32 float4 per token row
        float4 v = __ldg(reinterpret_cast<const float4*>(x + (size_t)tok * IN_F + k0) + kq);
        uint32_t h01, h23;
        asm("cvt.rn.f16x2.f32 %0, %1, %2;" : "=r"(h01) : "f"(v.y), "f"(v.x));
        asm("cvt.rn.f16x2.f32 %0, %1, %2;" : "=r"(h23) : "f"(v.w), "f"(v.z));
        asm volatile("st.shared.v2.b32 [%0], {%1,%2};"
                     :: "r"(sb + (uint32_t)(tok * XROW + kq * 8)), "r"(h01), "r"(h23) : "memory");
    }
    __syncthreads();

    const uint32_t xb0 = sb + (uint32_t)(g * XROW + 16 * t);         // tokens 0..7
    const uint32_t xb1 = sb + (uint32_t)((g + 8) * XROW + 16 * t);   // tokens 8..15

    // STEPS == 2: two explicit step bodies; no dead tail prefetch
    step_body(0, 1, true,  b0A, b0B, b1A, b1B, qA, qB, sA, sB, xb0, xb1, acc);
    step_body(1, 1, false, b1A, b1B, b0A, b0B, qA, qB, sA, sB, xb0, xb1, acc);

    // epilogue: 8 atomic adds into bias-initialized y (distinct addresses)
    const int tok0 = 2 * t;
    float* yA = y + rowA;
    float* yB = y + rowB;
    atomicAdd(yA + (size_t)(tok0    ) * OUT_F, acc[0][0]);
    atomicAdd(yA + (size_t)(tok0 + 1) * OUT_F, acc[0][1]);
    atomicAdd(yB + (size_t)(tok0    ) * OUT_F, acc[0][2]);
    atomicAdd(yB + (size_t)(tok0 + 1) * OUT_F, acc[0][3]);
    atomicAdd(yA + (size_t)(tok0 + 8) * OUT_F, acc[1][0]);
    atomicAdd(yA + (size_t)(tok0 + 9) * OUT_F, acc[1][1]);
    atomicAdd(yB + (size_t)(tok0 + 8) * OUT_F, acc[1][2]);
    atomicAdd(yB + (size_t)(tok0 + 9) * OUT_F, acc[1][3]);
}

extern "C" void kernel_launch(void* const* d_in, const int* in_sizes, int n_in,
                              void* d_out, int out_size)
{
    const float* x      = (const float*)d_in[0];
    const int*   qw     = (const int*)d_in[1];
    const float* scales = (const float*)d_in[2];
    const float* bias   = (const float*)d_in[3];
    float*       y      = (float*)d_out;

    yinit<<<TOK * OUT_F / 4 / 256, 256>>>(bias, y);
    qmma <<<dim3(OUT_F / TILE_M, KSPLIT), THREADS>>>(x, qw, scales, y);
}

// round 7
// speedup vs baseline: 2.5525x; 1.0072x over previous
#include <cuda_runtime.h>
#include <cuda_fp16.h>
#include <cstdint>

#define OUT_F   11008
#define IN_F    4096
#define TOK     16
#define TILE_M  128
#define KSPLIT  32
#define KCHUNK  (IN_F / KSPLIT)    // 128
#define THREADS 256
#define XROW    (KCHUNK * 2 + 16)  // 272 B padded row
#define YSROW   132                // floats; bank-conflict-free stage tile

// ---------------- helpers ----------------
__device__ __forceinline__ uint32_t smem_u32(const void* p) {
    uint32_t a;
    asm("{ .reg .u64 t; cvta.to.shared.u64 t, %1; cvt.u32.u64 %0, t; }" : "=r"(a) : "l"(p));
    return a;
}
__device__ __forceinline__ unsigned long long pack2(unsigned int lo, unsigned int hi) {
    unsigned long long d; asm("mov.b64 %0, {%1,%2};" : "=l"(d) : "r"(lo), "r"(hi)); return d;
}
__device__ __forceinline__ unsigned long long add2(unsigned long long a, unsigned long long b) {
    unsigned long long d; asm("add.rn.f32x2 %0, %1, %2;" : "=l"(d) : "l"(a), "l"(b)); return d;
}
__device__ __forceinline__ unsigned long long mul2(unsigned long long a, unsigned long long b) {
    unsigned long long d; asm("mul.rn.f32x2 %0, %1, %2;" : "=l"(d) : "l"(a), "l"(b)); return d;
}
// q0,q1 in [0,15] -> fp16x2 {s*(q0-8), s*(q1-8)}; fp32-exact dequant, one fp16 round.
__device__ __forceinline__ uint32_t dqh(int q0, int q1, unsigned long long s2) {
    const unsigned long long M2 = pack2(0xCB000008u, 0xCB000008u); // -8388616.0f x2
    unsigned long long f = pack2(0x4B000000u | (unsigned)q0, 0x4B000000u | (unsigned)q1);
    unsigned long long w = mul2(add2(f, M2), s2);
    unsigned int l, h;
    asm("mov.b64 {%0,%1}, %2;" : "=r"(l), "=r"(h) : "l"(w));
    uint32_t r;
    asm("cvt.rn.f16x2.f32 %0, %1, %2;" : "=r"(r)
        : "f"(__uint_as_float(h)), "f"(__uint_as_float(l)));
    return r;
}
__device__ __forceinline__ void mma16816(float* c, uint32_t a0, uint32_t a1,
                                         uint32_t a2, uint32_t a3,
                                         uint32_t b0, uint32_t b1) {
    asm volatile(
        "mma.sync.aligned.m16n8k16.row.col.f32.f16.f16.f32 "
        "{%0,%1,%2,%3}, {%4,%5,%6,%7}, {%8,%9}, {%0,%1,%2,%3};"
        : "+f"(c[0]), "+f"(c[1]), "+f"(c[2]), "+f"(c[3])
        : "r"(a0), "r"(a1), "r"(a2), "r"(a3), "r"(b0), "r"(b1));
}

// ---------------- kernel 1: y = bias (broadcast over tokens) ----------------
__global__ void yinit(const float* __restrict__ bias, float* __restrict__ y)
{
    int i = blockIdx.x * 256 + threadIdx.x;      // float4 idx, 44032 total
    int tok = i / (OUT_F / 4);
    int o4  = i - tok * (OUT_F / 4);
    float4 b = __ldg(reinterpret_cast<const float4*>(bias) + o4);
    reinterpret_cast<float4*>(y)[i] = b;
}

// ---------------- kernel 2: fused convert + quantized GEMM -------------------
// k permutation within a 64-k step: c=(j,p) uses k = 64s + 32j + 8t + 4p + {0..3}
__device__ __forceinline__ void step_body(
    int s, int sn, bool pf,
    const int4 (&curA)[4], const int4 (&curB)[4],
    int4 (&nxtA)[4], int4 (&nxtB)[4],
    const int4* qA, const int4* qB,
    float2 scA, float2 scB,
    uint32_t xb0, uint32_t xb1,
    float (&acc)[2][4])
{
    if (pf) {
        // prefetch next step's A: 8 LDG.128, evict-first (streaming, zero reuse)
        #pragma unroll
        for (int j2 = 0; j2 < 4; j2++) {
            int idx = sn * 16 + (j2 >> 1) * 8 + (j2 & 1);
            nxtA[j2] = __ldcs(qA + idx);
            nxtB[j2] = __ldcs(qB + idx);
        }
    }

    // B fragments: 4x LDS.128 from fp16 x tile
    uint4 bh[2][2];
    #pragma unroll
    for (int j = 0; j < 2; j++) {
        asm volatile("ld.shared.v4.b32 {%0,%1,%2,%3}, [%4];"
            : "=r"(bh[0][j].x), "=r"(bh[0][j].y), "=r"(bh[0][j].z), "=r"(bh[0][j].w)
            : "r"(xb0 + (uint32_t)(s * 128 + 64 * j)));
        asm volatile("ld.shared.v4.b32 {%0,%1,%2,%3}, [%4];"
            : "=r"(bh[1][j].x), "=r"(bh[1][j].y), "=r"(bh[1][j].z), "=r"(bh[1][j].w)
            : "r"(xb1 + (uint32_t)(s * 128 + 64 * j)));
    }

    #pragma unroll
    for (int j = 0; j < 2; j++) {
        float sa = j ? scA.y : scA.x;
        float sb = j ? scB.y : scB.x;
        unsigned long long s2a = pack2(__float_as_uint(sa), __float_as_uint(sa));
        unsigned long long s2b = pack2(__float_as_uint(sb), __float_as_uint(sb));
        #pragma unroll
        for (int p = 0; p < 2; p++) {
            int4 va = curA[2 * j + p], vb = curB[2 * j + p];
            uint32_t a0 = dqh(va.x, va.y, s2a);
            uint32_t a2 = dqh(va.z, va.w, s2a);
            uint32_t a1 = dqh(vb.x, vb.y, s2b);
            uint32_t a3 = dqh(vb.z, vb.w, s2b);
            const uint32_t* b0 = reinterpret_cast<const uint32_t*>(&bh[0][j]);
            const uint32_t* b1 = reinterpret_cast<const uint32_t*>(&bh[1][j]);
            mma16816(acc[0], a0, a1, a2, a3, b0[2 * p], b0[2 * p + 1]);
            mma16816(acc[1], a0, a1, a2, a3, b1[2 * p], b1[2 * p + 1]);
        }
    }
}

__global__ void __launch_bounds__(THREADS, 4)
qmma(const float* __restrict__ x, const int* __restrict__ qw,
     const float* __restrict__ scales, float* __restrict__ y)
{
    __shared__ __align__(16) char  xs[TOK * XROW];   // 4.25 KB fp16 x tile
    __shared__ __align__(16) float ys[TOK * YSROW];  // 8.25 KB result stage
    const uint32_t sb = smem_u32(xs);

    const int tid = threadIdx.x;
    const int lane = tid & 31, wid = tid >> 5;
    const int g = lane >> 2, t = lane & 3;
    const int out0 = blockIdx.x * TILE_M;
    const int rowA = out0 + wid * 16 + g;
    const int rowB = rowA + 8;
    const int k0 = blockIdx.y * KCHUNK;

    const int4* qA = reinterpret_cast<const int4*>(qw + (size_t)rowA * IN_F + k0) + 2 * t;
    const int4* qB = reinterpret_cast<const int4*>(qw + (size_t)rowB * IN_F + k0) + 2 * t;
    const float2* sA = reinterpret_cast<const float2*>(scales + (size_t)rowA * (IN_F / 32) + k0 / 32);
    const float2* sB = reinterpret_cast<const float2*>(scales + (size_t)rowB * (IN_F / 32) + k0 / 32);

    float acc[2][4] = {};
    int4 b0A[4], b0B[4], b1A[4], b1B[4];

    // start the qweight DRAM stream immediately (before x conversion)
    #pragma unroll
    for (int j2 = 0; j2 < 4; j2++) {
        int idx = (j2 >> 1) * 8 + (j2 & 1);
        b0A[j2] = __ldcs(qA + idx);
        b0B[j2] = __ldcs(qB + idx);
    }
    // both steps' scales up front (latency fully hidden behind qweight stream)
    float2 scA0 = __ldg(sA + 0), scA1 = __ldg(sA + 1);
    float2 scB0 = __ldg(sB + 0), scB1 = __ldg(sB + 1);

    // fused x conversion: this CTA's 16x128 fp32 slice -> fp16 smem (2 float4/thread)
    #pragma unroll
    for (int it = 0; it < TOK * KCHUNK / 4 / THREADS; it++) {
        int i = tid + it * THREADS;                  // float4 slots
        int tok = i >> 5, kq = i & 31;               // 32 float4 per token row
        float4 v = __ldg(reinterpret_cast<const float4*>(x + (size_t)tok * IN_F + k0) + kq);
        uint32_t h01, h23;
        asm("cvt.rn.f16x2.f32 %0, %1, %2;" : "=r"(h01) : "f"(v.y), "f"(v.x));
        asm("cvt.rn.f16x2.f32 %0, %1, %2;" : "=r"(h23) : "f"(v.w), "f"(v.z));
        asm volatile("st.shared.v2.b32 [%0], {%1,%2};"
                     :: "r"(sb + (uint32_t)(tok * XROW + kq * 8)), "r"(h01), "r"(h23) : "memory");
    }
    __syncthreads();

    const uint32_t xb0 = sb + (uint32_t)(g * XROW + 16 * t);         // tokens 0..7
    const uint32_t xb1 = sb + (uint32_t)((g + 8) * XROW + 16 * t);   // tokens 8..15

    // two steps of 64 k; no dead tail prefetch
    step_body(0, 1, true,  b0A, b0B, b1A, b1B, qA, qB, scA0, scB0, xb0, xb1, acc);
    step_body(1, 1, false, b1A, b1B, b0A, b0B, qA, qB, scA1, scB1, xb0, xb1, acc);

    // ---- epilogue: stage 16x128 tile in smem, then coalesced vector reds ----
    {
        const int col = wid * 16 + g;        // rowA - out0
        const int tk = 2 * t;
        ys[(tk    ) * YSROW + col    ] = acc[0][0];
        ys[(tk + 1) * YSROW + col    ] = acc[0][1];
        ys[(tk    ) * YSROW + col + 8] = acc[0][2];
        ys[(tk + 1) * YSROW + col + 8] = acc[0][3];
        ys[(tk + 8) * YSROW + col    ] = acc[1][0];
        ys[(tk + 9) * YSROW + col    ] = acc[1][1];
        ys[(tk + 8) * YSROW + col + 8] = acc[1][2];
        ys[(tk + 9) * YSROW + col + 8] = acc[1][3];
    }
    __syncthreads();

    #pragma unroll
    for (int i = 0; i < 2; i++) {
        int idx = tid + i * THREADS;         // 0..511
        int tok = idx >> 5, o4 = idx & 31;
        float4 v = *reinterpret_cast<const float4*>(&ys[tok * YSROW + o4 * 4]);
        float* dst = y + (size_t)tok * OUT_F + out0 + o4 * 4;
        asm volatile("red.global.add.v4.f32 [%0], {%1,%2,%3,%4};"
                     :: "l"(dst), "f"(v.x), "f"(v.y), "f"(v.z), "f"(v.w) : "memory");
    }
}

extern "C" void kernel_launch(void* const* d_in, const int* in_sizes, int n_in,
                              void* d_out, int out_size)
{
    const float* x      = (const float*)d_in[0];
    const int*   qw     = (const int*)d_in[1];
    const float* scales = (const float*)d_in[2];
    const float* bias   = (const float*)d_in[3];
    float*       y      = (float*)d_out;

    yinit<<<TOK * OUT_F / 4 / 256, 256>>>(bias, y);
    qmma <<<dim3(OUT_F / TILE_M, KSPLIT), THREADS>>>(x, qw, scales, y);
}

// round 8
// speedup vs baseline: 2.7096x; 1.0615x over previous
#include <cuda_runtime.h>
#include <cuda_fp16.h>
#include <cstdint>

#define OUT_F   11008
#define IN_F    4096
#define TOK     16
#define TILE_M  128
#define KSPLIT  32
#define KCHUNK  (IN_F / KSPLIT)    // 128
#define THREADS 256
#define NCTA    592                // 148 SMs x 4 co-resident CTAs
#define NITEMS  ((OUT_F / TILE_M) * KSPLIT)   // 2752
#define XROW    (KCHUNK * 2 + 16)  // 272 B padded row
#define YSROW   132                // floats; bank-conflict-free stage tile

__device__ unsigned int g_ticket;

// ---------------- helpers ----------------
__device__ __forceinline__ uint32_t smem_u32(const void* p) {
    uint32_t a;
    asm("{ .reg .u64 t; cvta.to.shared.u64 t, %1; cvt.u32.u64 %0, t; }" : "=r"(a) : "l"(p));
    return a;
}
__device__ __forceinline__ unsigned long long pack2(unsigned int lo, unsigned int hi) {
    unsigned long long d; asm("mov.b64 %0, {%1,%2};" : "=l"(d) : "r"(lo), "r"(hi)); return d;
}
__device__ __forceinline__ unsigned long long add2(unsigned long long a, unsigned long long b) {
    unsigned long long d; asm("add.rn.f32x2 %0, %1, %2;" : "=l"(d) : "l"(a), "l"(b)); return d;
}
__device__ __forceinline__ unsigned long long mul2(unsigned long long a, unsigned long long b) {
    unsigned long long d; asm("mul.rn.f32x2 %0, %1, %2;" : "=l"(d) : "l"(a), "l"(b)); return d;
}
// q0,q1 in [0,15] -> fp16x2 {s*(q0-8), s*(q1-8)}; fp32-exact dequant, one fp16 round.
__device__ __forceinline__ uint32_t dqh(int q0, int q1, unsigned long long s2) {
    const unsigned long long M2 = pack2(0xCB000008u, 0xCB000008u); // -8388616.0f x2
    unsigned long long f = pack2(0x4B000000u | (unsigned)q0, 0x4B000000u | (unsigned)q1);
    unsigned long long w = mul2(add2(f, M2), s2);
    unsigned int l, h;
    asm("mov.b64 {%0,%1}, %2;" : "=r"(l), "=r"(h) : "l"(w));
    uint32_t r;
    asm("cvt.rn.f16x2.f32 %0, %1, %2;" : "=r"(r)
        : "f"(__uint_as_float(h)), "f"(__uint_as_float(l)));
    return r;
}
__device__ __forceinline__ void mma16816(float* c, uint32_t a0, uint32_t a1,
                                         uint32_t a2, uint32_t a3,
                                         uint32_t b0, uint32_t b1) {
    asm volatile(
        "mma.sync.aligned.m16n8k16.row.col.f32.f16.f16.f32 "
        "{%0,%1,%2,%3}, {%4,%5,%6,%7}, {%8,%9}, {%0,%1,%2,%3};"
        : "+f"(c[0]), "+f"(c[1]), "+f"(c[2]), "+f"(c[3])
        : "r"(a0), "r"(a1), "r"(a2), "r"(a3), "r"(b0), "r"(b1));
}

// ---------------- kernel 1: y = bias, ticket = 0 ----------------
__global__ void yinit(const float* __restrict__ bias, float* __restrict__ y)
{
    if (blockIdx.x == 0 && threadIdx.x == 0) g_ticket = 0u;
    int i = blockIdx.x * 256 + threadIdx.x;      // float4 idx, 44032 total
    int tok = i / (OUT_F / 4);
    int o4  = i - tok * (OUT_F / 4);
    float4 b = __ldg(reinterpret_cast<const float4*>(bias) + o4);
    reinterpret_cast<float4*>(y)[i] = b;
}

// ---------------- kernel 2: persistent fused convert + quantized GEMM --------
// k permutation within a 64-k step: c=(j,p) uses k = 64s + 32j + 8t + 4p + {0..3}
__device__ __forceinline__ void step_body(
    int s, int sn, bool pf,
    const int4 (&curA)[4], const int4 (&curB)[4],
    int4 (&nxtA)[4], int4 (&nxtB)[4],
    const int4* qA, const int4* qB,
    float2 scA, float2 scB,
    uint32_t xb0, uint32_t xb1,
    float (&acc)[2][4])
{
    if (pf) {
        // prefetch next step's A: 8 LDG.128, evict-first (streaming, zero reuse)
        #pragma unroll
        for (int j2 = 0; j2 < 4; j2++) {
            int idx = sn * 16 + (j2 >> 1) * 8 + (j2 & 1);
            nxtA[j2] = __ldcs(qA + idx);
            nxtB[j2] = __ldcs(qB + idx);
        }
    }

    // B fragments: 4x LDS.128 from fp16 x tile
    uint4 bh[2][2];
    #pragma unroll
    for (int j = 0; j < 2; j++) {
        asm volatile("ld.shared.v4.b32 {%0,%1,%2,%3}, [%4];"
            : "=r"(bh[0][j].x), "=r"(bh[0][j].y), "=r"(bh[0][j].z), "=r"(bh[0][j].w)
            : "r"(xb0 + (uint32_t)(s * 128 + 64 * j)));
        asm volatile("ld.shared.v4.b32 {%0,%1,%2,%3}, [%4];"
            : "=r"(bh[1][j].x), "=r"(bh[1][j].y), "=r"(bh[1][j].z), "=r"(bh[1][j].w)
            : "r"(xb1 + (uint32_t)(s * 128 + 64 * j)));
    }

    #pragma unroll
    for (int j = 0; j < 2; j++) {
        float sa = j ? scA.y : scA.x;
        float sb = j ? scB.y : scB.x;
        unsigned long long s2a = pack2(__float_as_uint(sa), __float_as_uint(sa));
        unsigned long long s2b = pack2(__float_as_uint(sb), __float_as_uint(sb));
        #pragma unroll
        for (int p = 0; p < 2; p++) {
            int4 va = curA[2 * j + p], vb = curB[2 * j + p];
            uint32_t a0 = dqh(va.x, va.y, s2a);
            uint32_t a2 = dqh(va.z, va.w, s2a);
            uint32_t a1 = dqh(vb.x, vb.y, s2b);
            uint32_t a3 = dqh(vb.z, vb.w, s2b);
            const uint32_t* b0 = reinterpret_cast<const uint32_t*>(&bh[0][j]);
            const uint32_t* b1 = reinterpret_cast<const uint32_t*>(&bh[1][j]);
            mma16816(acc[0], a0, a1, a2, a3, b0[2 * p], b0[2 * p + 1]);
            mma16816(acc[1], a0, a1, a2, a3, b1[2 * p], b1[2 * p + 1]);
        }
    }
}

__global__ void __launch_bounds__(THREADS, 4)
qmma(const float* __restrict__ x, const int* __restrict__ qw,
     const float* __restrict__ scales, float* __restrict__ y)
{
    __shared__ __align__(16) char  xs[TOK * XROW];   // 4.25 KB fp16 x tile
    __shared__ __align__(16) float ys[TOK * YSROW];  // 8.25 KB result stage
    __shared__ int sh_item;
    const uint32_t sb = smem_u32(xs);

    const int tid = threadIdx.x;
    const int lane = tid & 31, wid = tid >> 5;
    const int g = lane >> 2, t = lane & 3;

    const uint32_t xb0 = sb + (uint32_t)(g * XROW + 16 * t);         // tokens 0..7
    const uint32_t xb1 = sb + (uint32_t)((g + 8) * XROW + 16 * t);   // tokens 8..15

    for (;;) {
        if (tid == 0) sh_item = (int)atomicAdd(&g_ticket, 1u);
        __syncthreads();                       // publish item; fence prev epilogue
        const int itm = sh_item;
        if (itm >= NITEMS) return;

        const int out0 = (itm >> 5) * TILE_M;  // 86 tiles
        const int k0   = (itm & 31) * KCHUNK;  // 32 k-chunks
        const int rowA = out0 + wid * 16 + g;
        const int rowB = rowA + 8;

        const int4* qA = reinterpret_cast<const int4*>(qw + (size_t)rowA * IN_F + k0) + 2 * t;
        const int4* qB = reinterpret_cast<const int4*>(qw + (size_t)rowB * IN_F + k0) + 2 * t;
        const float2* sA = reinterpret_cast<const float2*>(scales + (size_t)rowA * (IN_F / 32) + k0 / 32);
        const float2* sB = reinterpret_cast<const float2*>(scales + (size_t)rowB * (IN_F / 32) + k0 / 32);

        float acc[2][4] = {};
        int4 b0A[4], b0B[4], b1A[4], b1B[4];

        // start the qweight DRAM stream immediately (before x conversion)
        #pragma unroll
        for (int j2 = 0; j2 < 4; j2++) {
            int idx = (j2 >> 1) * 8 + (j2 & 1);
            b0A[j2] = __ldcs(qA + idx);
            b0B[j2] = __ldcs(qB + idx);
        }
        // both steps' scales up front (latency hidden behind qweight stream)
        float2 scA0 = __ldg(sA + 0), scA1 = __ldg(sA + 1);
        float2 scB0 = __ldg(sB + 0), scB1 = __ldg(sB + 1);

        // fused x conversion: 16x128 fp32 slice -> fp16 smem (2 float4/thread)
        #pragma unroll
        for (int it = 0; it < TOK * KCHUNK / 4 / THREADS; it++) {
            int i = tid + it * THREADS;                  // float4 slots
            int tok = i >> 5, kq = i & 31;               // 32 float4 per token row
            float4 v = __ldg(reinterpret_cast<const float4*>(x + (size_t)tok * IN_F + k0) + kq);
            uint32_t h01, h23;
            asm("cvt.rn.f16x2.f32 %0, %1, %2;" : "=r"(h01) : "f"(v.y), "f"(v.x));
            asm("cvt.rn.f16x2.f32 %0, %1, %2;" : "=r"(h23) : "f"(v.w), "f"(v.z));
            asm volatile("st.shared.v2.b32 [%0], {%1,%2};"
                         :: "r"(sb + (uint32_t)(tok * XROW + kq * 8)), "r"(h01), "r"(h23) : "memory");
        }
        __syncthreads();

        // two steps of 64 k; no dead tail prefetch
        step_body(0, 1, true,  b0A, b0B, b1A, b1B, qA, qB, scA0, scB0, xb0, xb1, acc);
        step_body(1, 1, false, b1A, b1B, b0A, b0B, qA, qB, scA1, scB1, xb0, xb1, acc);

        // ---- epilogue: stage 16x128 tile in smem, then coalesced vector reds ----
        {
            const int col = wid * 16 + g;        // rowA - out0
            const int tk = 2 * t;
            ys[(tk    ) * YSROW + col    ] = acc[0][0];
            ys[(tk + 1) * YSROW + col    ] = acc[0][1];
            ys[(tk    ) * YSROW + col + 8] = acc[0][2];
            ys[(tk + 1) * YSROW + col + 8] = acc[0][3];
            ys[(tk + 8) * YSROW + col    ] = acc[1][0];
            ys[(tk + 9) * YSROW + col    ] = acc[1][1];
            ys[(tk + 8) * YSROW + col + 8] = acc[1][2];
            ys[(tk + 9) * YSROW + col + 8] = acc[1][3];
        }
        __syncthreads();

        #pragma unroll
        for (int i = 0; i < 2; i++) {
            int idx = tid + i * THREADS;         // 0..511
            int tok = idx >> 5, o4 = idx & 31;
            float4 v = *reinterpret_cast<const float4*>(&ys[tok * YSROW + o4 * 4]);
            float* dst = y + (size_t)tok * OUT_F + out0 + o4 * 4;
            asm volatile("red.global.add.v4.f32 [%0], {%1,%2,%3,%4};"
                         :: "l"(dst), "f"(v.x), "f"(v.y), "f"(v.z), "f"(v.w) : "memory");
        }
    }
}

extern "C" void kernel_launch(void* const* d_in, const int* in_sizes, int n_in,
                              void* d_out, int out_size)
{
    const float* x      = (const float*)d_in[0];
    const int*   qw     = (const int*)d_in[1];
    const float* scales = (const float*)d_in[2];
    const float* bias   = (const float*)d_in[3];
    float*       y      = (float*)d_out;

    yinit<<<TOK * OUT_F / 4 / 256, 256>>>(bias, y);
    qmma <<<NCTA, THREADS>>>(x, qw, scales, y);
}